// round 8
// baseline (speedup 1.0000x reference)
#include <cuda_runtime.h>
#include <math.h>

#define BATCH 4
#define CHANS 3
#define HDIM 512
#define WDIM 512
#define NPLANES 32
#define MAX_COC 50.0f
#define KMAX 31
#define HALO 15
#define NSYM 16

#define R 4
#define BTX 32
#define BTY 8
#define NTHREADS (BTX*BTY)          // 256
#define OUTROWS (BTY*R)             // 32
#define TILE_H (OUTROWS + 2*HALO)   // 62
#define NROWS (KMAX + R - 1)        // 34
#define NPQ 8

// Shifted/reversed smem copies (float offsets; strides all even -> 8B alignment holds)
#define STR_SA 48
#define STR_SB 46
#define OFF_SA 0                    // SA[sy*48 + i] = v(gy, bx0 + i),      i in [0,48)
#define OFF_SB (OFF_SA + TILE_H*STR_SA)   // SB[sy*46 + t] = v(gy, bx0+1+t),  t in [0,46)
#define OFF_RA (OFF_SB + TILE_H*STR_SB)   // RA[sy*46 + i] = v(gy, bx0+31-i), i in [0,46)
#define OFF_RB (OFF_RA + TILE_H*STR_SB)   // RB[sy*46 + t] = v(gy, bx0+30-t), t in [0,46)
#define OFF_GS (OFF_RB + TILE_H*STR_SB)   // gs[m*32 + p]
#define SMEM_FLOATS (OFF_GS + NSYM*NPLANES)   // 12044 floats = 48176 B <= 49152

typedef unsigned long long u64;

__device__ __forceinline__ u64 pk(float lo, float hi) {
    u64 r; asm("mov.b64 %0, {%1, %2};" : "=l"(r) : "f"(lo), "f"(hi)); return r;
}
__device__ __forceinline__ void upk(float& lo, float& hi, u64 v) {
    asm("mov.b64 {%0, %1}, %2;" : "=f"(lo), "=f"(hi) : "l"(v));
}
__device__ __forceinline__ u64 ffma2(u64 a, u64 b, u64 c) {
    u64 d; asm("fma.rn.f32x2 %0, %1, %2, %3;" : "=l"(d) : "l"(a), "l"(b), "l"(c)); return d;
}
__device__ __forceinline__ u64 fmul2(u64 a, u64 b) {
    u64 d; asm("mul.rn.f32x2 %0, %1, %2;" : "=l"(d) : "l"(a), "l"(b)); return d;
}
__device__ __forceinline__ u64 fadd2(u64 a, u64 b) {
    u64 d; asm("add.rn.f32x2 %0, %1, %2;" : "=l"(d) : "l"(a), "l"(b)); return d;
}
__device__ __forceinline__ u64 lds64(unsigned int a) {
    u64 v; asm("ld.shared.b64 %0, [%1];" : "=l"(v) : "r"(a)); return v;
}

__global__ __launch_bounds__(NTHREADS, 2) void dof_kernel(
    const float* __restrict__ img,
    const float* __restrict__ coc,
    float* __restrict__ out)
{
    __shared__ float smem[SMEM_FLOATS];

    const int tx = threadIdx.x, ty = threadIdx.y;
    const int tid = ty * BTX + tx;
    const int bx0 = blockIdx.x * BTX;
    const int by0 = blockIdx.y * OUTROWS;
    const int z   = blockIdx.z;            // z = b*CHANS + ch
    const int b   = z / CHANS;
    const int planeHW = HDIM * WDIM;
    const float step = MAX_COC / (float)(NPLANES - 1);

    // ---- Per-plane symmetric Gaussian half table gs[m][p] ----
    if (tid < NPLANES) {
        const int p = tid;
        float g[KMAX];
        if (p == 0) {
            #pragma unroll
            for (int j = 0; j < KMAX; j++) g[j] = 0.f;
            g[HALO] = 1.f;
        } else {
            const float cocp  = (float)p * step;
            const float sigma = cocp / 2.355f;
            int k = (int)(2.f * cocp + 1.f);
            if ((k & 1) == 0) k++;
            k = min(k, KMAX);
            const int half = k >> 1;
            const float inv2s2 = 1.f / (2.f * sigma * sigma);
            float s = 0.f;
            #pragma unroll
            for (int j = 0; j < KMAX; j++) {
                const int d = j - HALO;
                const int ad = (d < 0) ? -d : d;
                float v = (ad <= half) ? expf(-(float)(d*d) * inv2s2) : 0.f;
                g[j] = v; s += v;
            }
            const float inv = 1.f / s;
            #pragma unroll
            for (int j = 0; j < KMAX; j++) g[j] *= inv;
        }
        #pragma unroll
        for (int m = 0; m < NSYM; m++) smem[OFF_GS + m * NPLANES + p] = g[HALO + m];
    }

    // ---- Build 4 shifted/reversed tile copies (this block's channel only) ----
    const float* imgP = img + (size_t)z * planeHW;
    // SA: 62 x 48
    for (int idx = tid; idx < TILE_H * 48; idx += NTHREADS) {
        const int sy = idx / 48, i = idx - sy * 48;
        const int gy = by0 - HALO + sy;
        const int gx = bx0 + i;
        const bool okY = (gy >= 0) & (gy < HDIM);
        smem[OFF_SA + sy * STR_SA + i] =
            (okY & (gx < WDIM)) ? imgP[gy * WDIM + gx] : 0.f;
    }
    // SB / RA / RB: 62 x 46 each
    for (int idx = tid; idx < TILE_H * 46; idx += NTHREADS) {
        const int sy = idx / 46, t = idx - sy * 46;
        const int gy = by0 - HALO + sy;
        const bool okY = (gy >= 0) & (gy < HDIM);
        const int rowbase = gy * WDIM;
        int gx1 = bx0 + 1 + t;                       // SB
        smem[OFF_SB + sy * STR_SB + t] =
            (okY & (gx1 < WDIM)) ? imgP[rowbase + gx1] : 0.f;
        int gx2 = bx0 + 31 - t;                      // RA
        smem[OFF_RA + sy * STR_SB + t] =
            (okY & (gx2 >= 0) & (gx2 < WDIM)) ? imgP[rowbase + gx2] : 0.f;
        int gx3 = bx0 + 30 - t;                      // RB
        smem[OFF_RB + sy * STR_SB + t] =
            (okY & (gx3 >= 0) & (gx3 < WDIM)) ? imgP[rowbase + gx3] : 0.f;
    }
    __syncthreads();

    const int x   = bx0 + tx;
    const int tyR = ty * R;

    // ---- Per-output plane + packed symmetric horizontal weights ----
    int pj[R];
    u64 hp[R][NPQ];
    #pragma unroll
    for (int j = 0; j < R; j++) {
        const int y = by0 + tyR + j;
        float c = coc[b * planeHW + y * WDIM + x];
        int p = (int)floorf(c / step + 0.5f);
        p = max(0, min(NPLANES - 1, p));
        pj[j] = p;
        // q=0 pair: center counted twice in sp[0].lo -> halve h0
        hp[j][0] = pk(smem[OFF_GS + 0 * NPLANES + p] * 0.5f,
                      smem[OFF_GS + 1 * NPLANES + p]);
        #pragma unroll
        for (int q = 1; q < NPQ; q++) {
            hp[j][q] = pk(smem[OFF_GS + (2*q)     * NPLANES + p],
                          smem[OFF_GS + (2*q + 1) * NPLANES + p]);
        }
    }

    // ---- Per-lane aligned base addresses (bytes) for L / R symmetric reads ----
    unsigned int smem_base = (unsigned int)__cvta_generic_to_shared(smem);
    const bool evenLane = ((tx & 1) == 0);
    // R side: R[m] = v(bx0 + tx + m)
    int rBaseF = evenLane ? (OFF_SA + tx)       : (OFF_SB + (tx - 1));
    int rStr   = evenLane ? STR_SA              : STR_SB;
    // L side: L[m] = v(bx0 + tx - m)
    int lBaseF = evenLane ? (OFF_RB + (30 - tx)) : (OFF_RA + (31 - tx));
    const int lStr = STR_SB;

    unsigned int rA = smem_base + (unsigned int)(rBaseF + tyR * rStr) * 4u;
    unsigned int lA = smem_base + (unsigned int)(lBaseF + tyR * lStr) * 4u;
    const unsigned int rInc = (unsigned int)rStr * 4u;
    const unsigned int lInc = (unsigned int)lStr * 4u;

    u64 acc[R];
    #pragma unroll
    for (int j = 0; j < R; j++) acc[j] = pk(0.f, 0.f);

    #pragma unroll 1
    for (int rr = 0; rr < NROWS; rr++) {
        // symmetric packed pre-adds: sp[q] = {L2q + R2q, L2q1 + R2q1}
        u64 sp[NPQ];
        #pragma unroll
        for (int q = 0; q < NPQ; q++) {
            sp[q] = fadd2(lds64(lA + 8u*q), lds64(rA + 8u*q));
        }
        #pragma unroll
        for (int j = 0; j < R; j++) {
            const int vy = rr - j;                        // [-3, 33]
            const bool valid = (vy >= 0) & (vy <= KMAX - 1);
            int m = vy - HALO; m = (m < 0) ? -m : m;
            m = min(m, NSYM - 1);
            float gv = 0.f;
            if (valid) gv = smem[OFF_GS + m * NPLANES + pj[j]];
            u64 rsp = fmul2(hp[j][0], sp[0]);
            #pragma unroll
            for (int q = 1; q < NPQ; q++) rsp = ffma2(hp[j][q], sp[q], rsp);
            acc[j] = ffma2(pk(gv, gv), rsp, acc[j]);
        }
        rA += rInc; lA += lInc;
    }

    #pragma unroll
    for (int j = 0; j < R; j++) {
        float lo, hi; upk(lo, hi, acc[j]);
        const int y = by0 + tyR + j;
        out[(size_t)z * planeHW + y * WDIM + x] = lo + hi;
    }
}

extern "C" void kernel_launch(void* const* d_in, const int* in_sizes, int n_in,
                              void* d_out, int out_size)
{
    const float* img = (const float*)d_in[0];   // [4,3,512,512]
    const float* coc = (const float*)d_in[1];   // [4,1,512,512]
    float* out = (float*)d_out;                 // [4,3,512,512]

    dim3 block(BTX, BTY);
    dim3 grid(WDIM / BTX, HDIM / OUTROWS, BATCH * CHANS);
    dof_kernel<<<grid, block>>>(img, coc, out);
}

// round 9
// speedup vs baseline: 1.6316x; 1.6316x over previous
#include <cuda_runtime.h>
#include <math.h>

#define BATCH 4
#define CHANS 3
#define HDIM 512
#define WDIM 512
#define NPLANES 32
#define MAX_COC 50.0f
#define KMAX 31
#define HALO 15
#define NSYM 16

#define R 4
#define BTX 32
#define BTY 8
#define NTHREADS (BTX*BTY)          // 256
#define OUTROWS (BTY*R)             // 32
#define TILE_W (BTX + 2*HALO)       // 62
#define TILE_H (OUTROWS + 2*HALO)   // 62
#define NROWS (KMAX + R - 1)        // 34
#define NPQ 8

typedef unsigned long long u64;

__device__ __forceinline__ u64 pk(float lo, float hi) {
    u64 r; asm("mov.b64 %0, {%1, %2};" : "=l"(r) : "f"(lo), "f"(hi)); return r;
}
__device__ __forceinline__ void upk(float& lo, float& hi, u64 v) {
    asm("mov.b64 {%0, %1}, %2;" : "=f"(lo), "=f"(hi) : "l"(v));
}
__device__ __forceinline__ u64 ffma2(u64 a, u64 b, u64 c) {
    u64 d; asm("fma.rn.f32x2 %0, %1, %2, %3;" : "=l"(d) : "l"(a), "l"(b), "l"(c)); return d;
}
__device__ __forceinline__ u64 fmul2(u64 a, u64 b) {
    u64 d; asm("mul.rn.f32x2 %0, %1, %2;" : "=l"(d) : "l"(a), "l"(b)); return d;
}

__global__ __launch_bounds__(NTHREADS, 2) void dof_kernel(
    const float* __restrict__ img,
    const float* __restrict__ coc,
    float* __restrict__ out)
{
    __shared__ float tile[TILE_H * TILE_W];              // one channel: 15376 B
    __shared__ float gs[NSYM * NPLANES];                 // gs[m*32+p]: 2048 B

    const int tx = threadIdx.x, ty = threadIdx.y;
    const int tid = ty * BTX + tx;
    const int bx0 = blockIdx.x * BTX;
    const int by0 = blockIdx.y * OUTROWS;
    const int z   = blockIdx.z;            // z = b*CHANS + ch
    const int b   = z / CHANS;
    const int planeHW = HDIM * WDIM;
    const float step = MAX_COC / (float)(NPLANES - 1);

    // ---- Per-plane symmetric Gaussian half table gs[m][p] ----
    if (tid < NPLANES) {
        const int p = tid;
        float g[KMAX];
        if (p == 0) {
            #pragma unroll
            for (int j = 0; j < KMAX; j++) g[j] = 0.f;
            g[HALO] = 1.f;
        } else {
            const float cocp  = (float)p * step;
            const float sigma = cocp / 2.355f;
            int k = (int)(2.f * cocp + 1.f);
            if ((k & 1) == 0) k++;
            k = min(k, KMAX);
            const int half = k >> 1;
            const float inv2s2 = 1.f / (2.f * sigma * sigma);
            float s = 0.f;
            #pragma unroll
            for (int j = 0; j < KMAX; j++) {
                const int d = j - HALO;
                const int ad = (d < 0) ? -d : d;
                float v = (ad <= half) ? expf(-(float)(d*d) * inv2s2) : 0.f;
                g[j] = v; s += v;
            }
            const float inv = 1.f / s;
            #pragma unroll
            for (int j = 0; j < KMAX; j++) g[j] *= inv;
        }
        #pragma unroll
        for (int m = 0; m < NSYM; m++) gs[m * NPLANES + p] = g[HALO + m];
    }

    // ---- Cooperative tile load (this block's channel, zero-pad) ----
    const float* imgP = img + (size_t)z * planeHW;
    for (int idx = tid; idx < TILE_H * TILE_W; idx += NTHREADS) {
        const int sy = idx / TILE_W;
        const int sx = idx - sy * TILE_W;
        const int gy = by0 - HALO + sy;
        const int gx = bx0 - HALO + sx;
        const bool inb = (gy >= 0) & (gy < HDIM) & (gx >= 0) & (gx < WDIM);
        tile[idx] = inb ? imgP[gy * WDIM + gx] : 0.f;
    }
    __syncthreads();

    const int x   = bx0 + tx;
    const int tyR = ty * R;

    // ---- Per-output plane + packed symmetric horizontal weights ----
    const float* gcol[R];    // per-output column base into gs (indexed by m*32)
    u64 hp[R][NPQ];          // 64 registers
    #pragma unroll
    for (int j = 0; j < R; j++) {
        const int y = by0 + tyR + j;
        float c = coc[b * planeHW + y * WDIM + x];
        int p = (int)floorf(c / step + 0.5f);
        p = max(0, min(NPLANES - 1, p));
        gcol[j] = &gs[p];
        #pragma unroll
        for (int q = 0; q < NPQ; q++) {
            hp[j][q] = pk(gs[(2*q) * NPLANES + p],
                          gs[(2*q + 1) * NPLANES + p]);
        }
    }

    u64 acc[R];
    #pragma unroll
    for (int j = 0; j < R; j++) acc[j] = pk(0.f, 0.f);

    // ---- Main gather: FULL unroll -> compile-time m/validity, imm-offset gv ----
    #pragma unroll
    for (int rr = 0; rr < NROWS; rr++) {
        const float* rowp = tile + (tyR + rr) * TILE_W + tx;
        // symmetric pre-adds shared by all R outputs:
        // sp[0] = {t[c], t[c-1]+t[c+1]}, sp[q] = {t[c-2q]+t[c+2q], t[c-2q-1]+t[c+2q+1]}
        u64 sp[NPQ];
        {
            const float s0 = rowp[HALO];
            const float s1 = rowp[HALO-1] + rowp[HALO+1];
            sp[0] = pk(s0, s1);
            #pragma unroll
            for (int q = 1; q < NPQ; q++) {
                const int m0 = 2*q, m1 = 2*q + 1;
                const float a0 = rowp[HALO-m0] + rowp[HALO+m0];
                const float a1 = rowp[HALO-m1] + rowp[HALO+m1];
                sp[q] = pk(a0, a1);
            }
        }
        #pragma unroll
        for (int j = 0; j < R; j++) {
            const int vy = rr - j;                 // compile-time per (rr,j)
            if (vy >= 0 && vy <= KMAX - 1) {
                const int m = (vy >= HALO) ? (vy - HALO) : (HALO - vy);
                const float gv = gcol[j][m * NPLANES];   // LDS, imm offset
                u64 rsp = fmul2(hp[j][0], sp[0]);
                #pragma unroll
                for (int q = 1; q < NPQ; q++) rsp = ffma2(hp[j][q], sp[q], rsp);
                acc[j] = ffma2(pk(gv, gv), rsp, acc[j]);
            }
        }
    }

    #pragma unroll
    for (int j = 0; j < R; j++) {
        float lo, hi; upk(lo, hi, acc[j]);
        const int y = by0 + tyR + j;
        out[(size_t)z * planeHW + y * WDIM + x] = lo + hi;
    }
}

extern "C" void kernel_launch(void* const* d_in, const int* in_sizes, int n_in,
                              void* d_out, int out_size)
{
    const float* img = (const float*)d_in[0];   // [4,3,512,512]
    const float* coc = (const float*)d_in[1];   // [4,1,512,512]
    float* out = (float*)d_out;                 // [4,3,512,512]

    dim3 block(BTX, BTY);
    dim3 grid(WDIM / BTX, HDIM / OUTROWS, BATCH * CHANS);
    dof_kernel<<<grid, block>>>(img, coc, out);
}

// round 11
// speedup vs baseline: 1.8031x; 1.1051x over previous
#include <cuda_runtime.h>
#include <math.h>

#define BATCH 4
#define CHANS 3
#define HDIM 512
#define WDIM 512
#define NPLANES 32
#define MAX_COC 50.0f
#define KMAX 31
#define HALO 15
#define NSYM 16

#define R 8                          // outputs per thread, stacked in y
#define BTX 32
#define BTY 4
#define NTHREADS (BTX*BTY)           // 128
#define OUTROWS (BTY*R)              // 32
#define TILE_W (BTX + 2*HALO)        // 62
#define TILE_H (OUTROWS + 2*HALO)    // 62
#define NROWS (KMAX + R - 1)         // 38
#define NPQ 8

typedef unsigned long long u64;

__device__ __forceinline__ u64 pk(float lo, float hi) {
    u64 r; asm("mov.b64 %0, {%1, %2};" : "=l"(r) : "f"(lo), "f"(hi)); return r;
}
__device__ __forceinline__ void upk(float& lo, float& hi, u64 v) {
    asm("mov.b64 {%0, %1}, %2;" : "=f"(lo), "=f"(hi) : "l"(v));
}
__device__ __forceinline__ u64 ffma2(u64 a, u64 b, u64 c) {
    u64 d; asm("fma.rn.f32x2 %0, %1, %2, %3;" : "=l"(d) : "l"(a), "l"(b), "l"(c)); return d;
}
__device__ __forceinline__ u64 fmul2(u64 a, u64 b) {
    u64 d; asm("mul.rn.f32x2 %0, %1, %2;" : "=l"(d) : "l"(a), "l"(b)); return d;
}

__global__ __launch_bounds__(NTHREADS, 2) void dof_kernel(
    const float* __restrict__ img,
    const float* __restrict__ coc,
    float* __restrict__ out)
{
    __shared__ float tile[TILE_H * TILE_W];              // 15376 B
    __shared__ float gs[NSYM * NPLANES];                 // gs[m*32+p]: 2048 B

    const int tx = threadIdx.x, ty = threadIdx.y;
    const int tid = ty * BTX + tx;
    const int bx0 = blockIdx.x * BTX;
    const int by0 = blockIdx.y * OUTROWS;
    const int z   = blockIdx.z;            // z = b*CHANS + ch
    const int b   = z / CHANS;
    const int planeHW = HDIM * WDIM;
    const float step = MAX_COC / (float)(NPLANES - 1);

    // ---- Per-plane symmetric Gaussian half table gs[m][p] ----
    if (tid < NPLANES) {
        const int p = tid;
        float g[KMAX];
        if (p == 0) {
            #pragma unroll
            for (int j = 0; j < KMAX; j++) g[j] = 0.f;
            g[HALO] = 1.f;
        } else {
            const float cocp  = (float)p * step;
            const float sigma = cocp / 2.355f;
            int k = (int)(2.f * cocp + 1.f);
            if ((k & 1) == 0) k++;
            k = min(k, KMAX);
            const int half = k >> 1;
            const float inv2s2 = 1.f / (2.f * sigma * sigma);
            float s = 0.f;
            #pragma unroll
            for (int j = 0; j < KMAX; j++) {
                const int d = j - HALO;
                const int ad = (d < 0) ? -d : d;
                float v = (ad <= half) ? expf(-(float)(d*d) * inv2s2) : 0.f;
                g[j] = v; s += v;
            }
            const float inv = 1.f / s;
            #pragma unroll
            for (int j = 0; j < KMAX; j++) g[j] *= inv;
        }
        #pragma unroll
        for (int m = 0; m < NSYM; m++) gs[m * NPLANES + p] = g[HALO + m];
    }

    // ---- Cooperative tile load (this block's channel, zero-pad) ----
    const float* imgP = img + (size_t)z * planeHW;
    for (int idx = tid; idx < TILE_H * TILE_W; idx += NTHREADS) {
        const int sy = idx / TILE_W;
        const int sx = idx - sy * TILE_W;
        const int gy = by0 - HALO + sy;
        const int gx = bx0 - HALO + sx;
        const bool inb = (gy >= 0) & (gy < HDIM) & (gx >= 0) & (gx < WDIM);
        tile[idx] = inb ? imgP[gy * WDIM + gx] : 0.f;
    }
    __syncthreads();

    const int x   = bx0 + tx;
    const int tyR = ty * R;

    // ---- Per-output plane + packed symmetric horizontal weights ----
    const float* gcol[R];    // per-output column base into gs (indexed by m*32)
    u64 hp[R][NPQ];          // 128 registers of weights
    #pragma unroll
    for (int j = 0; j < R; j++) {
        const int y = by0 + tyR + j;
        float c = coc[b * planeHW + y * WDIM + x];
        int p = (int)floorf(c / step + 0.5f);
        p = max(0, min(NPLANES - 1, p));
        gcol[j] = &gs[p];
        #pragma unroll
        for (int q = 0; q < NPQ; q++) {
            hp[j][q] = pk(gs[(2*q) * NPLANES + p],
                          gs[(2*q + 1) * NPLANES + p]);
        }
    }

    u64 acc[R];
    #pragma unroll
    for (int j = 0; j < R; j++) acc[j] = pk(0.f, 0.f);

    // ---- Main gather: FULL unroll -> compile-time m/validity, imm-offset gv ----
    #pragma unroll
    for (int rr = 0; rr < NROWS; rr++) {
        const float* rowp = tile + (tyR + rr) * TILE_W + tx;
        // symmetric pre-adds shared by all R outputs:
        // sp[0] = {t[c], t[c-1]+t[c+1]}, sp[q] = {t[c-2q]+t[c+2q], t[c-2q-1]+t[c+2q+1]}
        u64 sp[NPQ];
        {
            const float s0 = rowp[HALO];
            const float s1 = rowp[HALO-1] + rowp[HALO+1];
            sp[0] = pk(s0, s1);
            #pragma unroll
            for (int q = 1; q < NPQ; q++) {
                const int m0 = 2*q, m1 = 2*q + 1;
                const float a0 = rowp[HALO-m0] + rowp[HALO+m0];
                const float a1 = rowp[HALO-m1] + rowp[HALO+m1];
                sp[q] = pk(a0, a1);
            }
        }
        #pragma unroll
        for (int j = 0; j < R; j++) {
            const int vy = rr - j;                 // compile-time per (rr,j)
            if (vy >= 0 && vy <= KMAX - 1) {
                const int m = (vy >= HALO) ? (vy - HALO) : (HALO - vy);
                const float gv = gcol[j][m * NPLANES];   // LDS broadcast, imm offset
                u64 rsp = fmul2(hp[j][0], sp[0]);
                #pragma unroll
                for (int q = 1; q < NPQ; q++) rsp = ffma2(hp[j][q], sp[q], rsp);
                acc[j] = ffma2(pk(gv, gv), rsp, acc[j]);
            }
        }
    }

    #pragma unroll
    for (int j = 0; j < R; j++) {
        float lo, hi; upk(lo, hi, acc[j]);
        const int y = by0 + tyR + j;
        out[(size_t)z * planeHW + y * WDIM + x] = lo + hi;
    }
}

extern "C" void kernel_launch(void* const* d_in, const int* in_sizes, int n_in,
                              void* d_out, int out_size)
{
    const float* img = (const float*)d_in[0];   // [4,3,512,512]
    const float* coc = (const float*)d_in[1];   // [4,1,512,512]
    float* out = (float*)d_out;                 // [4,3,512,512]

    dim3 block(BTX, BTY);
    dim3 grid(WDIM / BTX, HDIM / OUTROWS, BATCH * CHANS);
    dof_kernel<<<grid, block>>>(img, coc, out);
}

// round 12
// speedup vs baseline: 1.9905x; 1.1039x over previous
#include <cuda_runtime.h>
#include <math.h>

#define BATCH 4
#define CHANS 3
#define HDIM 512
#define WDIM 512
#define NPLANES 32
#define MAX_COC 50.0f
#define KMAX 31
#define HALO 15
#define NSYM 16

#define R 8                          // outputs per thread, stacked in y
#define BTX 32
#define BTY 4
#define NTHREADS (BTX*BTY)           // 128
#define OUTROWS (BTY*R)              // 32
#define TILE_W (BTX + 2*HALO)        // 62
#define TILE_H (OUTROWS + 2*HALO)    // 62
#define NROWS (KMAX + R - 1)         // 38
#define NPQ 8

typedef unsigned long long u64;

__device__ __forceinline__ u64 pk(float lo, float hi) {
    u64 r; asm("mov.b64 %0, {%1, %2};" : "=l"(r) : "f"(lo), "f"(hi)); return r;
}
__device__ __forceinline__ void upk(float& lo, float& hi, u64 v) {
    asm("mov.b64 {%0, %1}, %2;" : "=f"(lo), "=f"(hi) : "l"(v));
}
__device__ __forceinline__ u64 ffma2(u64 a, u64 b, u64 c) {
    u64 d; asm("fma.rn.f32x2 %0, %1, %2, %3;" : "=l"(d) : "l"(a), "l"(b), "l"(c)); return d;
}
__device__ __forceinline__ u64 fmul2(u64 a, u64 b) {
    u64 d; asm("mul.rn.f32x2 %0, %1, %2;" : "=l"(d) : "l"(a), "l"(b)); return d;
}

__global__ __launch_bounds__(NTHREADS, 3) void dof_kernel(
    const float* __restrict__ img,
    const float* __restrict__ coc,
    float* __restrict__ out)
{
    __shared__ float tile[TILE_H * TILE_W];              // 15376 B
    __shared__ float gs[NSYM * NPLANES];                 // gs[m*32+p]: 2048 B

    const int tx = threadIdx.x, ty = threadIdx.y;
    const int tid = ty * BTX + tx;
    const int bx0 = blockIdx.x * BTX;
    const int by0 = blockIdx.y * OUTROWS;
    const int z   = blockIdx.z;            // z = b*CHANS + ch
    const int b   = z / CHANS;
    const int planeHW = HDIM * WDIM;
    const float step = MAX_COC / (float)(NPLANES - 1);

    // ---- Per-plane symmetric Gaussian half table gs[m][p] ----
    if (tid < NPLANES) {
        const int p = tid;
        float g[KMAX];
        if (p == 0) {
            #pragma unroll
            for (int j = 0; j < KMAX; j++) g[j] = 0.f;
            g[HALO] = 1.f;
        } else {
            const float cocp  = (float)p * step;
            const float sigma = cocp / 2.355f;
            int k = (int)(2.f * cocp + 1.f);
            if ((k & 1) == 0) k++;
            k = min(k, KMAX);
            const int half = k >> 1;
            const float inv2s2 = 1.f / (2.f * sigma * sigma);
            float s = 0.f;
            #pragma unroll
            for (int j = 0; j < KMAX; j++) {
                const int d = j - HALO;
                const int ad = (d < 0) ? -d : d;
                float v = (ad <= half) ? expf(-(float)(d*d) * inv2s2) : 0.f;
                g[j] = v; s += v;
            }
            const float inv = 1.f / s;
            #pragma unroll
            for (int j = 0; j < KMAX; j++) g[j] *= inv;
        }
        #pragma unroll
        for (int m = 0; m < NSYM; m++) gs[m * NPLANES + p] = g[HALO + m];
    }

    // ---- Cooperative tile load (this block's channel, zero-pad) ----
    const float* imgP = img + (size_t)z * planeHW;
    for (int idx = tid; idx < TILE_H * TILE_W; idx += NTHREADS) {
        const int sy = idx / TILE_W;
        const int sx = idx - sy * TILE_W;
        const int gy = by0 - HALO + sy;
        const int gx = bx0 - HALO + sx;
        const bool inb = (gy >= 0) & (gy < HDIM) & (gx >= 0) & (gx < WDIM);
        tile[idx] = inb ? imgP[gy * WDIM + gx] : 0.f;
    }
    __syncthreads();

    const int x   = bx0 + tx;
    const int tyR = ty * R;

    // ---- Per-output plane + packed symmetric horizontal weights ----
    const float* gcol[R];    // per-output column base into gs (indexed by m*32)
    u64 hp[R][NPQ];          // 128 registers of weights
    #pragma unroll
    for (int j = 0; j < R; j++) {
        const int y = by0 + tyR + j;
        float c = coc[b * planeHW + y * WDIM + x];
        int p = (int)floorf(c / step + 0.5f);
        p = max(0, min(NPLANES - 1, p));
        gcol[j] = &gs[p];
        #pragma unroll
        for (int q = 0; q < NPQ; q++) {
            hp[j][q] = pk(gs[(2*q) * NPLANES + p],
                          gs[(2*q + 1) * NPLANES + p]);
        }
    }

    u64 acc[R];
    #pragma unroll
    for (int j = 0; j < R; j++) acc[j] = pk(0.f, 0.f);

    // ---- Main gather: full unroll, q-outer / j-inner to shrink live set ----
    #pragma unroll
    for (int rr = 0; rr < NROWS; rr++) {
        const float* rowp = tile + (tyR + rr) * TILE_W + tx;
        u64 rsp[R];
        // q = 0 : sp0 = {t[c], t[c-1]+t[c+1]}
        {
            const u64 sp0 = pk(rowp[HALO], rowp[HALO-1] + rowp[HALO+1]);
            #pragma unroll
            for (int j = 0; j < R; j++) {
                const int vy = rr - j;
                if (vy >= 0 && vy <= KMAX - 1)
                    rsp[j] = fmul2(hp[j][0], sp0);
            }
        }
        // q = 1..7 : sp = {t[c-2q]+t[c+2q], t[c-2q-1]+t[c+2q+1]}
        #pragma unroll
        for (int q = 1; q < NPQ; q++) {
            const int m0 = 2*q, m1 = 2*q + 1;
            const u64 sp = pk(rowp[HALO-m0] + rowp[HALO+m0],
                              rowp[HALO-m1] + rowp[HALO+m1]);
            #pragma unroll
            for (int j = 0; j < R; j++) {
                const int vy = rr - j;
                if (vy >= 0 && vy <= KMAX - 1)
                    rsp[j] = ffma2(hp[j][q], sp, rsp[j]);
            }
        }
        // vertical weight + accumulate
        #pragma unroll
        for (int j = 0; j < R; j++) {
            const int vy = rr - j;
            if (vy >= 0 && vy <= KMAX - 1) {
                const int m = (vy >= HALO) ? (vy - HALO) : (HALO - vy);
                const float gv = gcol[j][m * NPLANES];   // LDS broadcast/distinct-bank
                acc[j] = ffma2(pk(gv, gv), rsp[j], acc[j]);
            }
        }
    }

    #pragma unroll
    for (int j = 0; j < R; j++) {
        float lo, hi; upk(lo, hi, acc[j]);
        const int y = by0 + tyR + j;
        out[(size_t)z * planeHW + y * WDIM + x] = lo + hi;
    }
}

extern "C" void kernel_launch(void* const* d_in, const int* in_sizes, int n_in,
                              void* d_out, int out_size)
{
    const float* img = (const float*)d_in[0];   // [4,3,512,512]
    const float* coc = (const float*)d_in[1];   // [4,1,512,512]
    float* out = (float*)d_out;                 // [4,3,512,512]

    dim3 block(BTX, BTY);
    dim3 grid(WDIM / BTX, HDIM / OUTROWS, BATCH * CHANS);
    dof_kernel<<<grid, block>>>(img, coc, out);
}